// round 4
// baseline (speedup 1.0000x reference)
#include <cuda_runtime.h>
#include <cuda_fp16.h>
#include <cstdint>

// ============================================================================
// out[M,N] = x[M,K] @ w_bin[N,K]^T + bias[N]
//   w_bin = (w < mean-std || w > mean+std) ? w : sign(w)   (std: ddof=1)
// Shapes: M=16384, K=4096, N=4096 fp32.
// Engine: fp16 convert + classic mma.sync.m16n8k16 pipelined GEMM (base sm_103
// ISA only — tcgen05/TMA are arch-'a' features the harness toolchain rejects).
// ============================================================================

#define MAXM 16384
#define MAXN 4096
#define MAXK 4096

__device__ __half g_Xh[(size_t)MAXM * MAXK];   // 128 MiB scratch
__device__ __half g_Wb[(size_t)MAXN * MAXK];   // 32 MiB scratch
__device__ double g_part[2048];
__device__ float  g_thresh[2];

// ---------------------------------------------------------------- stats ----
__global__ void stats1_kernel(const float* __restrict__ w, int n) {
    __shared__ double ss[256], sq[256];
    double s = 0.0, q = 0.0;
    for (int i = blockIdx.x * blockDim.x + threadIdx.x; i < n; i += gridDim.x * blockDim.x) {
        double v = (double)w[i];
        s += v; q += v * v;
    }
    ss[threadIdx.x] = s; sq[threadIdx.x] = q;
    __syncthreads();
    for (int o = 128; o > 0; o >>= 1) {
        if (threadIdx.x < o) { ss[threadIdx.x] += ss[threadIdx.x + o]; sq[threadIdx.x] += sq[threadIdx.x + o]; }
        __syncthreads();
    }
    if (threadIdx.x == 0) { g_part[blockIdx.x * 2] = ss[0]; g_part[blockIdx.x * 2 + 1] = sq[0]; }
}

__global__ void stats2_kernel(int nparts, int n) {
    __shared__ double ss[256], sq[256];
    double s = 0.0, q = 0.0;
    for (int i = threadIdx.x; i < nparts; i += 256) { s += g_part[2 * i]; q += g_part[2 * i + 1]; }
    ss[threadIdx.x] = s; sq[threadIdx.x] = q;
    __syncthreads();
    for (int o = 128; o > 0; o >>= 1) {
        if (threadIdx.x < o) { ss[threadIdx.x] += ss[threadIdx.x + o]; sq[threadIdx.x] += sq[threadIdx.x + o]; }
        __syncthreads();
    }
    if (threadIdx.x == 0) {
        double mean = ss[0] / (double)n;
        double var  = (sq[0] - ss[0] * ss[0] / (double)n) / (double)(n - 1);
        double sd = sqrt(var);
        g_thresh[0] = (float)(mean - sd);
        g_thresh[1] = (float)(mean + sd);
    }
}

__device__ __forceinline__ float binv(float w, float lo, float hi) {
    if (w < lo || w > hi) return w;
    return (w > 0.f) ? 1.f : ((w < 0.f) ? -1.f : 0.f);
}

__global__ void binarize_kernel(const float* __restrict__ w, int n4) {
    float lo = g_thresh[0], hi = g_thresh[1];
    const float4* w4 = (const float4*)w;
    __half2* o2 = (__half2*)g_Wb;
    for (int i = blockIdx.x * blockDim.x + threadIdx.x; i < n4; i += gridDim.x * blockDim.x) {
        float4 v = w4[i];
        o2[2 * i]     = __floats2half2_rn(binv(v.x, lo, hi), binv(v.y, lo, hi));
        o2[2 * i + 1] = __floats2half2_rn(binv(v.z, lo, hi), binv(v.w, lo, hi));
    }
}

__global__ void xconv_kernel(const float* __restrict__ x, int n4) {
    const float4* x4 = (const float4*)x;
    __half2* o2 = (__half2*)g_Xh;
    for (int i = blockIdx.x * blockDim.x + threadIdx.x; i < n4; i += gridDim.x * blockDim.x) {
        float4 v = x4[i];
        o2[2 * i]     = __floats2half2_rn(v.x, v.y);
        o2[2 * i + 1] = __floats2half2_rn(v.z, v.w);
    }
}

// ---------------------------------------------------------------- GEMM -----
// CTA tile 128(M) x 256(N), BK=32, 4-stage cp.async pipeline, 256 threads.
// Warps: 2(M) x 4(N); warp tile 64x64 = 4 x 8 mma.m16n8k16 per k16-step.
// Smem rows padded to 80B (5x16B): ldmatrix phase-conflict-free.

#define BM 128
#define BN 256
#define BK 32
#define ROWB 80                       // bytes per smem row (32 fp16 + 8 pad)
#define STAGE_A (BM * ROWB)           // 10240
#define STAGE_B (BN * ROWB)           // 20480
#define STAGE   (STAGE_A + STAGE_B)   // 30720
#define NSTG 4
#define GEMM_SMEM (NSTG * STAGE)      // 122880

__device__ __forceinline__ uint32_t smem_u32(const void* p) {
    uint32_t a;
    asm("{ .reg .u64 t; cvta.to.shared.u64 t, %1; cvt.u32.u64 %0, t; }" : "=r"(a) : "l"(p));
    return a;
}
__device__ __forceinline__ void cp16(uint32_t s, const void* g) {
    asm volatile("cp.async.cg.shared.global [%0], [%1], 16;" :: "r"(s), "l"(g));
}
#define CP_COMMIT() asm volatile("cp.async.commit_group;" ::: "memory")
#define CP_WAIT2()  asm volatile("cp.async.wait_group %0;" :: "n"(2) : "memory")

#define LDSM4(r0, r1, r2, r3, addr) \
    asm volatile("ldmatrix.sync.aligned.m8n8.x4.shared.b16 {%0,%1,%2,%3}, [%4];" \
        : "=r"(r0), "=r"(r1), "=r"(r2), "=r"(r3) : "r"(addr))

__device__ __forceinline__ void mma16816(float* d, const uint32_t* a, const uint32_t* b) {
    asm volatile(
        "mma.sync.aligned.m16n8k16.row.col.f32.f16.f16.f32 "
        "{%0,%1,%2,%3}, {%4,%5,%6,%7}, {%8,%9}, {%0,%1,%2,%3};"
        : "+f"(d[0]), "+f"(d[1]), "+f"(d[2]), "+f"(d[3])
        : "r"(a[0]), "r"(a[1]), "r"(a[2]), "r"(a[3]), "r"(b[0]), "r"(b[1]));
}

__device__ __forceinline__ void issue_stage(
    uint32_t sb, int stage, const __half* __restrict__ gA,
    const __half* __restrict__ gB, int kt, int tid, int K)
{
    uint32_t sA = sb + stage * STAGE;
    uint32_t sB = sA + STAGE_A;
    const __half* ga = gA + kt * BK;
    #pragma unroll
    for (int j = 0; j < 2; j++) {                  // A: 128x32 = 512 chunks
        int cid = tid + j * 256;
        int r = cid >> 2, c = cid & 3;
        cp16(sA + r * ROWB + c * 16, ga + (size_t)r * K + c * 8);
    }
    const __half* gb = gB + kt * BK;
    #pragma unroll
    for (int j = 0; j < 4; j++) {                  // B: 256x32 = 1024 chunks
        int cid = tid + j * 256;
        int r = cid >> 2, c = cid & 3;
        cp16(sB + r * ROWB + c * 16, gb + (size_t)r * K + c * 8);
    }
}

__global__ void __launch_bounds__(256, 1)
gemm_kernel(float* __restrict__ out, const float* __restrict__ bias,
            const __half* __restrict__ A, const __half* __restrict__ B,
            int M, int N, int K)
{
    extern __shared__ char smem[];
    uint32_t sb = smem_u32(smem);

    int tid = threadIdx.x;
    int wid = tid >> 5, L = tid & 31;
    int warpM = wid >> 2, warpN = wid & 3;

    int NT = N / BN;
    int ntile = blockIdx.x % NT;                   // fast N => W stays L2-hot
    int mtile = blockIdx.x / NT;

    const __half* gA = A + (size_t)(mtile * BM) * K;
    const __half* gB = B + (size_t)(ntile * BN) * K;
    int KT = K / BK;                               // 128

    float acc[4][8][4];
    #pragma unroll
    for (int i = 0; i < 4; i++)
        #pragma unroll
        for (int j = 0; j < 8; j++)
            #pragma unroll
            for (int q = 0; q < 4; q++) acc[i][j][q] = 0.f;

    // prologue: fill 3 of 4 stages
    #pragma unroll
    for (int s = 0; s < NSTG - 1; s++) {
        issue_stage(sb, s, gA, gB, s, tid, K);
        CP_COMMIT();
    }

    // precomputed ldmatrix lane offsets
    int aRow = warpM * 64 + (L & 15);              // + mt*16
    int aCol = (L >> 4) << 3;                      // + ks*16
    int jb = L >> 3;
    int bRowBase = warpN * 64 + ((jb >> 1) << 3) + (L & 7);   // + p*16
    int bCol = (jb & 1) << 3;                      // + ks*16

    for (int kt = 0; kt < KT; kt++) {
        CP_WAIT2();
        __syncthreads();

        uint32_t sA = sb + (kt & 3) * STAGE;
        uint32_t sB = sA + STAGE_A;

        #pragma unroll
        for (int ks = 0; ks < 2; ks++) {
            uint32_t aF[4][4], bF[8][2];
            #pragma unroll
            for (int mt = 0; mt < 4; mt++) {
                uint32_t ad = sA + (aRow + mt * 16) * ROWB + (aCol + ks * 16) * 2;
                LDSM4(aF[mt][0], aF[mt][1], aF[mt][2], aF[mt][3], ad);
            }
            #pragma unroll
            for (int p = 0; p < 4; p++) {          // n-tile pairs (2p, 2p+1)
                uint32_t bd = sB + (bRowBase + p * 16) * ROWB + (bCol + ks * 16) * 2;
                uint32_t r0, r1, r2, r3;
                LDSM4(r0, r1, r2, r3, bd);
                bF[2 * p][0] = r0; bF[2 * p][1] = r1;
                bF[2 * p + 1][0] = r2; bF[2 * p + 1][1] = r3;
            }
            #pragma unroll
            for (int mt = 0; mt < 4; mt++)
                #pragma unroll
                for (int nt = 0; nt < 8; nt++)
                    mma16816(acc[mt][nt], aF[mt], bF[nt]);
        }

        if (kt + NSTG - 1 < KT)
            issue_stage(sb, (kt + NSTG - 1) & 3, gA, gB, kt + NSTG - 1, tid, K);
        CP_COMMIT();                               // commit every iter (tail!)
    }

    // ---------------- epilogue: direct fp32 stores + bias -----------------
    int rbase = mtile * BM + warpM * 64 + (L >> 2);
    int cbase = ntile * BN + warpN * 64 + (L & 3) * 2;

    float2 bv[8];
    #pragma unroll
    for (int nt = 0; nt < 8; nt++)
        bv[nt] = *(const float2*)(bias + cbase + nt * 8);

    #pragma unroll
    for (int mt = 0; mt < 4; mt++) {
        int r0 = rbase + mt * 16;
        #pragma unroll
        for (int nt = 0; nt < 8; nt++) {
            int c = cbase + nt * 8;
            float2 v0 = { acc[mt][nt][0] + bv[nt].x, acc[mt][nt][1] + bv[nt].y };
            float2 v1 = { acc[mt][nt][2] + bv[nt].x, acc[mt][nt][3] + bv[nt].y };
            *(float2*)(out + (size_t)r0 * N + c)       = v0;
            *(float2*)(out + (size_t)(r0 + 8) * N + c) = v1;
        }
    }
}

// ---------------------------------------------------------------- host -----
extern "C" void kernel_launch(void* const* d_in, const int* in_sizes, int n_in,
                              void* d_out, int out_size)
{
    const float* x    = (const float*)d_in[0];
    const float* w    = (const float*)d_in[1];
    const float* bias = (const float*)d_in[2];
    float* out = (float*)d_out;

    int N  = in_sizes[2];
    int K  = in_sizes[1] / N;
    int M  = in_sizes[0] / K;
    int nw = in_sizes[1];
    int nx = in_sizes[0];

    stats1_kernel<<<1024, 256>>>(w, nw);
    stats2_kernel<<<1, 256>>>(1024, nw);
    binarize_kernel<<<2048, 256>>>(w, nw / 4);
    xconv_kernel<<<4096, 256>>>(x, nx / 4);

    void *pXh = nullptr, *pWb = nullptr;
    cudaGetSymbolAddress(&pXh, g_Xh);
    cudaGetSymbolAddress(&pWb, g_Wb);

    static int smem_set = 0;
    if (!smem_set) {
        cudaFuncSetAttribute(gemm_kernel, cudaFuncAttributeMaxDynamicSharedMemorySize, GEMM_SMEM);
        smem_set = 1;
    }

    int grid = (M / BM) * (N / BN);
    gemm_kernel<<<grid, 256, GEMM_SMEM>>>(out, bias, (const __half*)pXh,
                                          (const __half*)pWb, M, N, K);
}

// round 6
// speedup vs baseline: 1.0244x; 1.0244x over previous
#include <cuda_runtime.h>
#include <cuda_fp16.h>
#include <cstdint>

// ============================================================================
// out[M,N] = x[M,K] @ w_bin[N,K]^T + bias[N]
//   w_bin = (w < mean-std || w > mean+std) ? w : sign(w)   (std: ddof=1)
// Shapes: M=16384, K=4096, N=4096 fp32.
// Engine: fp16 convert + mma.sync.m16n8k16 pipelined GEMM (base sm_103 ISA).
// R6: R5 design with ROWB=144 (16B-aligned cp.async dsts; 136 crashed).
// ============================================================================

#define MAXM 16384
#define MAXN 4096
#define MAXK 4096

__device__ __half g_Xh[(size_t)MAXM * MAXK];   // 128 MiB scratch
__device__ __half g_Wb[(size_t)MAXN * MAXK];   // 32 MiB scratch
__device__ double g_part[2048];
__device__ float  g_thresh[2];

// ---------------------------------------------------------------- stats ----
__global__ void stats1_kernel(const float* __restrict__ w, int n) {
    __shared__ double ss[256], sq[256];
    double s = 0.0, q = 0.0;
    for (int i = blockIdx.x * blockDim.x + threadIdx.x; i < n; i += gridDim.x * blockDim.x) {
        double v = (double)w[i];
        s += v; q += v * v;
    }
    ss[threadIdx.x] = s; sq[threadIdx.x] = q;
    __syncthreads();
    for (int o = 128; o > 0; o >>= 1) {
        if (threadIdx.x < o) { ss[threadIdx.x] += ss[threadIdx.x + o]; sq[threadIdx.x] += sq[threadIdx.x + o]; }
        __syncthreads();
    }
    if (threadIdx.x == 0) { g_part[blockIdx.x * 2] = ss[0]; g_part[blockIdx.x * 2 + 1] = sq[0]; }
}

__global__ void stats2_kernel(int nparts, int n) {
    __shared__ double ss[256], sq[256];
    double s = 0.0, q = 0.0;
    for (int i = threadIdx.x; i < nparts; i += 256) { s += g_part[2 * i]; q += g_part[2 * i + 1]; }
    ss[threadIdx.x] = s; sq[threadIdx.x] = q;
    __syncthreads();
    for (int o = 128; o > 0; o >>= 1) {
        if (threadIdx.x < o) { ss[threadIdx.x] += ss[threadIdx.x + o]; sq[threadIdx.x] += sq[threadIdx.x + o]; }
        __syncthreads();
    }
    if (threadIdx.x == 0) {
        double mean = ss[0] / (double)n;
        double var  = (sq[0] - ss[0] * ss[0] / (double)n) / (double)(n - 1);
        double sd = sqrt(var);
        g_thresh[0] = (float)(mean - sd);
        g_thresh[1] = (float)(mean + sd);
    }
}

__device__ __forceinline__ float binv(float w, float lo, float hi) {
    if (w < lo || w > hi) return w;
    return (w > 0.f) ? 1.f : ((w < 0.f) ? -1.f : 0.f);
}

__global__ void binarize_kernel(const float* __restrict__ w, int n4) {
    float lo = g_thresh[0], hi = g_thresh[1];
    const float4* w4 = (const float4*)w;
    __half2* o2 = (__half2*)g_Wb;
    for (int i = blockIdx.x * blockDim.x + threadIdx.x; i < n4; i += gridDim.x * blockDim.x) {
        float4 v = w4[i];
        o2[2 * i]     = __floats2half2_rn(binv(v.x, lo, hi), binv(v.y, lo, hi));
        o2[2 * i + 1] = __floats2half2_rn(binv(v.z, lo, hi), binv(v.w, lo, hi));
    }
}

__global__ void xconv_kernel(const float* __restrict__ x, int n4) {
    const float4* x4 = (const float4*)x;
    __half2* o2 = (__half2*)g_Xh;
    for (int i = blockIdx.x * blockDim.x + threadIdx.x; i < n4; i += gridDim.x * blockDim.x) {
        float4 v = x4[i];
        o2[2 * i]     = __floats2half2_rn(v.x, v.y);
        o2[2 * i + 1] = __floats2half2_rn(v.z, v.w);
    }
}

// ---------------------------------------------------------------- GEMM -----
// CTA tile 256(M) x 128(N), BK=64, 3-stage cp.async pipeline, 256 threads.
// Warps 4(M) x 2(N); warp tile 64x64 = 4 x 8 mma.m16n8k16 per k16-step,
// 4 k16-steps per stage, fragment double-buffering across k16-steps.
// Smem rows 144B (64 fp16 + 16B pad): 16B-aligned AND phase-conflict-free
// (144 mod 128 = 16 -> 8 tile rows cover all 32 banks exactly once).

#define BM 256
#define BN 128
#define BK 64
#define ROWB 144                      // bytes per smem row (64 fp16 + 16 pad)
#define STAGE_A (BM * ROWB)           // 36864
#define STAGE_B (BN * ROWB)           // 18432
#define STAGE   (STAGE_A + STAGE_B)   // 55296
#define NSTG 3
#define GEMM_SMEM (NSTG * STAGE)      // 165888

__device__ __forceinline__ uint32_t smem_u32(const void* p) {
    uint32_t a;
    asm("{ .reg .u64 t; cvta.to.shared.u64 t, %1; cvt.u32.u64 %0, t; }" : "=r"(a) : "l"(p));
    return a;
}
__device__ __forceinline__ void cp16(uint32_t s, const void* g) {
    asm volatile("cp.async.cg.shared.global [%0], [%1], 16;" :: "r"(s), "l"(g));
}
#define CP_COMMIT() asm volatile("cp.async.commit_group;" ::: "memory")
#define CP_WAIT1()  asm volatile("cp.async.wait_group %0;" :: "n"(1) : "memory")

#define LDSM4(r0, r1, r2, r3, addr) \
    asm volatile("ldmatrix.sync.aligned.m8n8.x4.shared.b16 {%0,%1,%2,%3}, [%4];" \
        : "=r"(r0), "=r"(r1), "=r"(r2), "=r"(r3) : "r"(addr))

__device__ __forceinline__ void mma16816(float* d, const uint32_t* a, const uint32_t* b) {
    asm volatile(
        "mma.sync.aligned.m16n8k16.row.col.f32.f16.f16.f32 "
        "{%0,%1,%2,%3}, {%4,%5,%6,%7}, {%8,%9}, {%0,%1,%2,%3};"
        : "+f"(d[0]), "+f"(d[1]), "+f"(d[2]), "+f"(d[3])
        : "r"(a[0]), "r"(a[1]), "r"(a[2]), "r"(a[3]), "r"(b[0]), "r"(b[1]));
}

// One BK=64 stage: A 256x64 fp16 (2048 x 16B chunks), B 128x64 (1024 chunks).
__device__ __forceinline__ void issue_stage(
    uint32_t sb, int stage, const __half* __restrict__ gA,
    const __half* __restrict__ gB, int kt, int tid, int K)
{
    uint32_t sA = sb + stage * STAGE;
    uint32_t sB = sA + STAGE_A;
    const __half* ga = gA + (size_t)kt * BK;
    #pragma unroll
    for (int j = 0; j < 8; j++) {                  // A: 2048 chunks / 256 thr
        int cid = tid + j * 256;
        int r = cid >> 3, c = cid & 7;
        cp16(sA + r * ROWB + c * 16, ga + (size_t)r * K + c * 8);
    }
    const __half* gb = gB + (size_t)kt * BK;
    #pragma unroll
    for (int j = 0; j < 4; j++) {                  // B: 1024 chunks / 256 thr
        int cid = tid + j * 256;
        int r = cid >> 3, c = cid & 7;
        cp16(sB + r * ROWB + c * 16, gb + (size_t)r * K + c * 8);
    }
}

__global__ void __launch_bounds__(256, 1)
gemm_kernel(float* __restrict__ out, const float* __restrict__ bias,
            const __half* __restrict__ A, const __half* __restrict__ B,
            int M, int N, int K)
{
    extern __shared__ char smem[];
    uint32_t sb = smem_u32(smem);

    int tid = threadIdx.x;
    int wid = tid >> 5, L = tid & 31;
    int warpM = wid >> 1, warpN = wid & 1;         // 4(M) x 2(N)

    int NT = N / BN;                               // 32
    int ntile = blockIdx.x % NT;                   // fast N => W stays L2-hot
    int mtile = blockIdx.x / NT;

    const __half* gA = A + (size_t)(mtile * BM) * K;
    const __half* gB = B + (size_t)(ntile * BN) * K;
    int KT = K / BK;                               // 64

    float acc[4][8][4];
    #pragma unroll
    for (int i = 0; i < 4; i++)
        #pragma unroll
        for (int j = 0; j < 8; j++)
            #pragma unroll
            for (int q = 0; q < 4; q++) acc[i][j][q] = 0.f;

    // prologue: fill 2 of 3 stages
    issue_stage(sb, 0, gA, gB, 0, tid, K); CP_COMMIT();
    issue_stage(sb, 1, gA, gB, 1, tid, K); CP_COMMIT();

    // ldmatrix lane offsets (validated in R3/R4)
    int aRow = warpM * 64 + (L & 15);              // + mt*16
    int aCol = (L >> 4) << 3;                      // + ks*16
    int jb = L >> 3;
    int bRowBase = warpN * 64 + ((jb >> 1) << 3) + (L & 7);   // + p*16
    int bCol = (jb & 1) << 3;                      // + ks*16

    uint32_t aF[2][4][4], bF[2][8][2];

    int st = 0;                                    // stage of current kt
    for (int kt = 0; kt < KT; kt++) {
        CP_WAIT1();
        __syncthreads();

        // issue next-next stage first so cp.async overlaps all 4 ks-steps
        if (kt + 2 < KT) {
            int st2 = st + 2; if (st2 >= NSTG) st2 -= NSTG;
            issue_stage(sb, st2, gA, gB, kt + 2, tid, K);
        }
        CP_COMMIT();                               // commit every iter (tail!)

        uint32_t sA = sb + st * STAGE;
        uint32_t sB = sA + STAGE_A;

        // prefetch ks=0 fragments
        #pragma unroll
        for (int mt = 0; mt < 4; mt++) {
            uint32_t ad = sA + (aRow + mt * 16) * ROWB + aCol * 2;
            LDSM4(aF[0][mt][0], aF[0][mt][1], aF[0][mt][2], aF[0][mt][3], ad);
        }
        #pragma unroll
        for (int p = 0; p < 4; p++) {
            uint32_t bd = sB + (bRowBase + p * 16) * ROWB + bCol * 2;
            uint32_t r0, r1, r2, r3;
            LDSM4(r0, r1, r2, r3, bd);
            bF[0][2 * p][0] = r0; bF[0][2 * p][1] = r1;
            bF[0][2 * p + 1][0] = r2; bF[0][2 * p + 1][1] = r3;
        }

        #pragma unroll
        for (int ks = 0; ks < 4; ks++) {           // 4 x k16 within BK=64
            int cur = ks & 1, nxt = cur ^ 1;
            if (ks < 3) {                          // prefetch ks+1 fragments
                int kc = (ks + 1) * 16;
                #pragma unroll
                for (int mt = 0; mt < 4; mt++) {
                    uint32_t ad = sA + (aRow + mt * 16) * ROWB + (aCol + kc) * 2;
                    LDSM4(aF[nxt][mt][0], aF[nxt][mt][1], aF[nxt][mt][2], aF[nxt][mt][3], ad);
                }
                #pragma unroll
                for (int p = 0; p < 4; p++) {
                    uint32_t bd = sB + (bRowBase + p * 16) * ROWB + (bCol + kc) * 2;
                    uint32_t r0, r1, r2, r3;
                    LDSM4(r0, r1, r2, r3, bd);
                    bF[nxt][2 * p][0] = r0; bF[nxt][2 * p][1] = r1;
                    bF[nxt][2 * p + 1][0] = r2; bF[nxt][2 * p + 1][1] = r3;
                }
            }
            #pragma unroll
            for (int mt = 0; mt < 4; mt++)
                #pragma unroll
                for (int nt = 0; nt < 8; nt++)
                    mma16816(acc[mt][nt], aF[cur][mt], bF[cur][nt]);
        }

        if (++st == NSTG) st = 0;
    }

    // ---------------- epilogue: fp32 stores (streaming) + bias ------------
    int rbase = mtile * BM + warpM * 64 + (L >> 2);
    int cbase = ntile * BN + warpN * 64 + (L & 3) * 2;

    float2 bv[8];
    #pragma unroll
    for (int nt = 0; nt < 8; nt++)
        bv[nt] = *(const float2*)(bias + cbase + nt * 8);

    #pragma unroll
    for (int mt = 0; mt < 4; mt++) {
        int r0 = rbase + mt * 16;
        #pragma unroll
        for (int nt = 0; nt < 8; nt++) {
            int c = cbase + nt * 8;
            float2 v0 = { acc[mt][nt][0] + bv[nt].x, acc[mt][nt][1] + bv[nt].y };
            float2 v1 = { acc[mt][nt][2] + bv[nt].x, acc[mt][nt][3] + bv[nt].y };
            __stcs((float2*)(out + (size_t)r0 * N + c), v0);
            __stcs((float2*)(out + (size_t)(r0 + 8) * N + c), v1);
        }
    }
}

// ---------------------------------------------------------------- host -----
extern "C" void kernel_launch(void* const* d_in, const int* in_sizes, int n_in,
                              void* d_out, int out_size)
{
    const float* x    = (const float*)d_in[0];
    const float* w    = (const float*)d_in[1];
    const float* bias = (const float*)d_in[2];
    float* out = (float*)d_out;

    int N  = in_sizes[2];
    int K  = in_sizes[1] / N;
    int M  = in_sizes[0] / K;
    int nw = in_sizes[1];
    int nx = in_sizes[0];

    stats1_kernel<<<1024, 256>>>(w, nw);
    stats2_kernel<<<1, 256>>>(1024, nw);
    binarize_kernel<<<2048, 256>>>(w, nw / 4);
    xconv_kernel<<<4096, 256>>>(x, nx / 4);

    void *pXh = nullptr, *pWb = nullptr;
    cudaGetSymbolAddress(&pXh, g_Xh);
    cudaGetSymbolAddress(&pWb, g_Wb);

    cudaFuncSetAttribute(gemm_kernel, cudaFuncAttributeMaxDynamicSharedMemorySize, GEMM_SMEM);

    int grid = (M / BM) * (N / BN);
    gemm_kernel<<<grid, 256, GEMM_SMEM>>>(out, bias, (const __half*)pXh,
                                          (const __half*)pWb, M, N, K);
}

// round 8
// speedup vs baseline: 1.0457x; 1.0208x over previous
#include <cuda_runtime.h>
#include <cuda_fp16.h>
#include <cstdint>

// ============================================================================
// out[M,N] = x[M,K] @ w_bin[N,K]^T + bias[N]
//   w_bin = (w < mean-std || w > mean+std) ? w : sign(w)   (std: ddof=1)
// Shapes: M=16384, K=4096, N=4096 fp32.
// Engine: fp16 convert + mma.sync.m16n8k16 pipelined GEMM (base sm_103 ISA).
// R7: 512-thread CTA (4 warps/SMSP, warp tile 64x32) vs R6's 2 warps/SMSP;
//     stats2 fused into binarize; xconv first (gemm -> ncu capture slot).
// ============================================================================

#define MAXM 16384
#define MAXN 4096
#define MAXK 4096

__device__ __half g_Xh[(size_t)MAXM * MAXK];   // 128 MiB scratch
__device__ __half g_Wb[(size_t)MAXN * MAXK];   // 32 MiB scratch
__device__ double g_part[2048];

// ---------------------------------------------------------------- stats ----
__global__ void stats1_kernel(const float* __restrict__ w, int n) {
    __shared__ double ss[256], sq[256];
    double s = 0.0, q = 0.0;
    for (int i = blockIdx.x * blockDim.x + threadIdx.x; i < n; i += gridDim.x * blockDim.x) {
        double v = (double)w[i];
        s += v; q += v * v;
    }
    ss[threadIdx.x] = s; sq[threadIdx.x] = q;
    __syncthreads();
    for (int o = 128; o > 0; o >>= 1) {
        if (threadIdx.x < o) { ss[threadIdx.x] += ss[threadIdx.x + o]; sq[threadIdx.x] += sq[threadIdx.x + o]; }
        __syncthreads();
    }
    if (threadIdx.x == 0) { g_part[blockIdx.x * 2] = ss[0]; g_part[blockIdx.x * 2 + 1] = sq[0]; }
}

__device__ __forceinline__ float binv(float w, float lo, float hi) {
    if (w < lo || w > hi) return w;
    return (w > 0.f) ? 1.f : ((w < 0.f) ? -1.f : 0.f);
}

// binarize + final threshold reduce fused (each block redundantly reduces the
// 1024 partials — deterministic, a few us total).
__global__ void binarize_kernel(const float* __restrict__ w, int n4, int n) {
    __shared__ double ss[256], sq[256];
    __shared__ float thr[2];
    double s = 0.0, q = 0.0;
    for (int i = threadIdx.x; i < 1024; i += 256) { s += g_part[2 * i]; q += g_part[2 * i + 1]; }
    ss[threadIdx.x] = s; sq[threadIdx.x] = q;
    __syncthreads();
    for (int o = 128; o > 0; o >>= 1) {
        if (threadIdx.x < o) { ss[threadIdx.x] += ss[threadIdx.x + o]; sq[threadIdx.x] += sq[threadIdx.x + o]; }
        __syncthreads();
    }
    if (threadIdx.x == 0) {
        double mean = ss[0] / (double)n;
        double var  = (sq[0] - ss[0] * ss[0] / (double)n) / (double)(n - 1);
        double sd = sqrt(var);
        thr[0] = (float)(mean - sd);
        thr[1] = (float)(mean + sd);
    }
    __syncthreads();
    float lo = thr[0], hi = thr[1];
    const float4* w4 = (const float4*)w;
    __half2* o2 = (__half2*)g_Wb;
    for (int i = blockIdx.x * blockDim.x + threadIdx.x; i < n4; i += gridDim.x * blockDim.x) {
        float4 v = w4[i];
        o2[2 * i]     = __floats2half2_rn(binv(v.x, lo, hi), binv(v.y, lo, hi));
        o2[2 * i + 1] = __floats2half2_rn(binv(v.z, lo, hi), binv(v.w, lo, hi));
    }
}

__global__ void xconv_kernel(const float* __restrict__ x, int n4) {
    const float4* x4 = (const float4*)x;
    __half2* o2 = (__half2*)g_Xh;
    for (int i = blockIdx.x * blockDim.x + threadIdx.x; i < n4; i += gridDim.x * blockDim.x) {
        float4 v = x4[i];
        o2[2 * i]     = __floats2half2_rn(v.x, v.y);
        o2[2 * i + 1] = __floats2half2_rn(v.z, v.w);
    }
}

// ---------------------------------------------------------------- GEMM -----
// CTA tile 256(M) x 128(N), BK=64, 3-stage cp.async pipeline, 512 threads.
// Warps 4(M) x 4(N); warp tile 64x32 = 4 x 4 mma.m16n8k16 per k16-step.
// 4 warps/SMSP for latency hiding; single-buffered fragments.
// Smem rows 144B: 16B-aligned cp.async dsts, ldmatrix phase-conflict-free.

#define BM 256
#define BN 128
#define BK 64
#define ROWB 144
#define STAGE_A (BM * ROWB)           // 36864
#define STAGE_B (BN * ROWB)           // 18432
#define STAGE   (STAGE_A + STAGE_B)   // 55296
#define NSTG 3
#define GEMM_SMEM (NSTG * STAGE)      // 165888

__device__ __forceinline__ uint32_t smem_u32(const void* p) {
    uint32_t a;
    asm("{ .reg .u64 t; cvta.to.shared.u64 t, %1; cvt.u32.u64 %0, t; }" : "=r"(a) : "l"(p));
    return a;
}
__device__ __forceinline__ void cp16(uint32_t s, const void* g) {
    asm volatile("cp.async.cg.shared.global [%0], [%1], 16;" :: "r"(s), "l"(g));
}
#define CP_COMMIT() asm volatile("cp.async.commit_group;" ::: "memory")
#define CP_WAIT1()  asm volatile("cp.async.wait_group %0;" :: "n"(1) : "memory")

#define LDSM4(r0, r1, r2, r3, addr) \
    asm volatile("ldmatrix.sync.aligned.m8n8.x4.shared.b16 {%0,%1,%2,%3}, [%4];" \
        : "=r"(r0), "=r"(r1), "=r"(r2), "=r"(r3) : "r"(addr))

__device__ __forceinline__ void mma16816(float* d, const uint32_t* a, const uint32_t* b) {
    asm volatile(
        "mma.sync.aligned.m16n8k16.row.col.f32.f16.f16.f32 "
        "{%0,%1,%2,%3}, {%4,%5,%6,%7}, {%8,%9}, {%0,%1,%2,%3};"
        : "+f"(d[0]), "+f"(d[1]), "+f"(d[2]), "+f"(d[3])
        : "r"(a[0]), "r"(a[1]), "r"(a[2]), "r"(a[3]), "r"(b[0]), "r"(b[1]));
}

// One BK=64 stage: A 256x64 fp16 (2048 x 16B chunks), B 128x64 (1024 chunks).
__device__ __forceinline__ void issue_stage(
    uint32_t sb, int stage, const __half* __restrict__ gA,
    const __half* __restrict__ gB, int kt, int tid, int K)
{
    uint32_t sA = sb + stage * STAGE;
    uint32_t sB = sA + STAGE_A;
    const __half* ga = gA + (size_t)kt * BK;
    #pragma unroll
    for (int j = 0; j < 4; j++) {                  // A: 2048 chunks / 512 thr
        int cid = tid + j * 512;
        int r = cid >> 3, c = cid & 7;
        cp16(sA + r * ROWB + c * 16, ga + (size_t)r * K + c * 8);
    }
    const __half* gb = gB + (size_t)kt * BK;
    #pragma unroll
    for (int j = 0; j < 2; j++) {                  // B: 1024 chunks / 512 thr
        int cid = tid + j * 512;
        int r = cid >> 3, c = cid & 7;
        cp16(sB + r * ROWB + c * 16, gb + (size_t)r * K + c * 8);
    }
}

__global__ void __launch_bounds__(512, 1)
gemm_kernel(float* __restrict__ out, const float* __restrict__ bias,
            const __half* __restrict__ A, const __half* __restrict__ B,
            int M, int N, int K)
{
    extern __shared__ char smem[];
    uint32_t sb = smem_u32(smem);

    int tid = threadIdx.x;
    int wid = tid >> 5, L = tid & 31;
    int warpM = wid >> 2, warpN = wid & 3;         // 4(M) x 4(N)

    int NT = N / BN;                               // 32
    int ntile = blockIdx.x % NT;                   // fast N => W stays L2-hot
    int mtile = blockIdx.x / NT;

    const __half* gA = A + (size_t)(mtile * BM) * K;
    const __half* gB = B + (size_t)(ntile * BN) * K;
    int KT = K / BK;                               // 64

    float acc[4][4][4];
    #pragma unroll
    for (int i = 0; i < 4; i++)
        #pragma unroll
        for (int j = 0; j < 4; j++)
            #pragma unroll
            for (int q = 0; q < 4; q++) acc[i][j][q] = 0.f;

    // prologue: fill 2 of 3 stages
    issue_stage(sb, 0, gA, gB, 0, tid, K); CP_COMMIT();
    issue_stage(sb, 1, gA, gB, 1, tid, K); CP_COMMIT();

    // ldmatrix lane offsets (mapping validated R3-R6)
    int aRow = warpM * 64 + (L & 15);              // + mt*16
    int aCol = (L >> 4) << 3;                      // + ks*16
    int jb = L >> 3;
    int bRowBase = warpN * 32 + ((jb >> 1) << 3) + (L & 7);   // + p*16
    int bCol = (jb & 1) << 3;                      // + ks*16

    int st = 0;                                    // stage of current kt
    for (int kt = 0; kt < KT; kt++) {
        CP_WAIT1();
        __syncthreads();

        // issue next-next stage first so cp.async overlaps all 4 ks-steps
        if (kt + 2 < KT) {
            int st2 = st + 2; if (st2 >= NSTG) st2 -= NSTG;
            issue_stage(sb, st2, gA, gB, kt + 2, tid, K);
        }
        CP_COMMIT();                               // commit every iter (tail!)

        uint32_t sA = sb + st * STAGE;
        uint32_t sB = sA + STAGE_A;

        #pragma unroll
        for (int ks = 0; ks < 4; ks++) {           // 4 x k16 within BK=64
            uint32_t aF[4][4], bF[4][2];
            int kc = ks * 16;
            #pragma unroll
            for (int mt = 0; mt < 4; mt++) {
                uint32_t ad = sA + (aRow + mt * 16) * ROWB + (aCol + kc) * 2;
                LDSM4(aF[mt][0], aF[mt][1], aF[mt][2], aF[mt][3], ad);
            }
            #pragma unroll
            for (int p = 0; p < 2; p++) {          // n-tile pairs (2p, 2p+1)
                uint32_t bd = sB + (bRowBase + p * 16) * ROWB + (bCol + kc) * 2;
                uint32_t r0, r1, r2, r3;
                LDSM4(r0, r1, r2, r3, bd);
                bF[2 * p][0] = r0; bF[2 * p][1] = r1;
                bF[2 * p + 1][0] = r2; bF[2 * p + 1][1] = r3;
            }
            #pragma unroll
            for (int mt = 0; mt < 4; mt++)
                #pragma unroll
                for (int nt = 0; nt < 4; nt++)
                    mma16816(acc[mt][nt], aF[mt], bF[nt]);
        }

        if (++st == NSTG) st = 0;
    }

    // ---------------- epilogue: fp32 stores (streaming) + bias ------------
    int rbase = mtile * BM + warpM * 64 + (L >> 2);
    int cbase = ntile * BN + warpN * 32 + (L & 3) * 2;

    float2 bv[4];
    #pragma unroll
    for (int nt = 0; nt < 4; nt++)
        bv[nt] = *(const float2*)(bias + cbase + nt * 8);

    #pragma unroll
    for (int mt = 0; mt < 4; mt++) {
        int r0 = rbase + mt * 16;
        #pragma unroll
        for (int nt = 0; nt < 4; nt++) {
            int c = cbase + nt * 8;
            float2 v0 = { acc[mt][nt][0] + bv[nt].x, acc[mt][nt][1] + bv[nt].y };
            float2 v1 = { acc[mt][nt][2] + bv[nt].x, acc[mt][nt][3] + bv[nt].y };
            __stcs((float2*)(out + (size_t)r0 * N + c), v0);
            __stcs((float2*)(out + (size_t)(r0 + 8) * N + c), v1);
        }
    }
}

// ---------------------------------------------------------------- host -----
extern "C" void kernel_launch(void* const* d_in, const int* in_sizes, int n_in,
                              void* d_out, int out_size)
{
    const float* x    = (const float*)d_in[0];
    const float* w    = (const float*)d_in[1];
    const float* bias = (const float*)d_in[2];
    float* out = (float*)d_out;

    int N  = in_sizes[2];
    int K  = in_sizes[1] / N;
    int M  = in_sizes[0] / K;
    int nw = in_sizes[1];
    int nx = in_sizes[0];

    // Order: xconv first (independent); gemm is our 4th kernel so it lands in
    // the ncu capture slot that previously caught xconv.
    xconv_kernel<<<4096, 256>>>(x, nx / 4);
    stats1_kernel<<<1024, 256>>>(w, nw);
    binarize_kernel<<<2048, 256>>>(w, nw / 4, nw);

    void *pXh = nullptr, *pWb = nullptr;
    cudaGetSymbolAddress(&pXh, g_Xh);
    cudaGetSymbolAddress(&pWb, g_Wb);

    cudaFuncSetAttribute(gemm_kernel, cudaFuncAttributeMaxDynamicSharedMemorySize, GEMM_SMEM);

    int grid = (M / BM) * (N / BN);
    gemm_kernel<<<grid, 512, GEMM_SMEM>>>(out, bias, (const __half*)pXh,
                                          (const __half*)pWb, M, N, K);
}

// round 10
// speedup vs baseline: 1.0954x; 1.0475x over previous
#include <cuda_runtime.h>
#include <cuda_fp16.h>
#include <cstdint>

// ============================================================================
// out[M,N] = x[M,K] @ w_bin[N,K]^T + bias[N]
//   w_bin = (w < mean-std || w > mean+std) ? w : sign(w)   (std: ddof=1)
// Shapes: M=16384, K=4096, N=4096 fp32.
// Engine: fp16 convert + mma.sync.m16n8k16 pipelined GEMM (base sm_103 ISA).
// R9: 2 CTAs/SM (tile 128x128, 108KB smem, 256 thr) so one CTA's barrier
//     overlaps the other CTA's MMA stream. R8 showed tensor=61%, idle 39%
//     from per-kt full-CTA barrier serialization at 1 CTA/SM.
// ============================================================================

#define MAXM 16384
#define MAXN 4096
#define MAXK 4096

__device__ __half g_Xh[(size_t)MAXM * MAXK];   // 128 MiB scratch
__device__ __half g_Wb[(size_t)MAXN * MAXK];   // 32 MiB scratch
__device__ double g_part[2048];

// ---------------------------------------------------------------- stats ----
__global__ void stats1_kernel(const float* __restrict__ w, int n) {
    __shared__ double ss[256], sq[256];
    double s = 0.0, q = 0.0;
    for (int i = blockIdx.x * blockDim.x + threadIdx.x; i < n; i += gridDim.x * blockDim.x) {
        double v = (double)w[i];
        s += v; q += v * v;
    }
    ss[threadIdx.x] = s; sq[threadIdx.x] = q;
    __syncthreads();
    for (int o = 128; o > 0; o >>= 1) {
        if (threadIdx.x < o) { ss[threadIdx.x] += ss[threadIdx.x + o]; sq[threadIdx.x] += sq[threadIdx.x + o]; }
        __syncthreads();
    }
    if (threadIdx.x == 0) { g_part[blockIdx.x * 2] = ss[0]; g_part[blockIdx.x * 2 + 1] = sq[0]; }
}

__device__ __forceinline__ float binv(float w, float lo, float hi) {
    if (w < lo || w > hi) return w;
    return (w > 0.f) ? 1.f : ((w < 0.f) ? -1.f : 0.f);
}

// binarize + final threshold reduce fused (each block redundantly reduces the
// 1024 partials — deterministic, a few us total).
__global__ void binarize_kernel(const float* __restrict__ w, int n4, int n) {
    __shared__ double ss[256], sq[256];
    __shared__ float thr[2];
    double s = 0.0, q = 0.0;
    for (int i = threadIdx.x; i < 1024; i += 256) { s += g_part[2 * i]; q += g_part[2 * i + 1]; }
    ss[threadIdx.x] = s; sq[threadIdx.x] = q;
    __syncthreads();
    for (int o = 128; o > 0; o >>= 1) {
        if (threadIdx.x < o) { ss[threadIdx.x] += ss[threadIdx.x + o]; sq[threadIdx.x] += sq[threadIdx.x + o]; }
        __syncthreads();
    }
    if (threadIdx.x == 0) {
        double mean = ss[0] / (double)n;
        double var  = (sq[0] - ss[0] * ss[0] / (double)n) / (double)(n - 1);
        double sd = sqrt(var);
        thr[0] = (float)(mean - sd);
        thr[1] = (float)(mean + sd);
    }
    __syncthreads();
    float lo = thr[0], hi = thr[1];
    const float4* w4 = (const float4*)w;
    __half2* o2 = (__half2*)g_Wb;
    for (int i = blockIdx.x * blockDim.x + threadIdx.x; i < n4; i += gridDim.x * blockDim.x) {
        float4 v = w4[i];
        o2[2 * i]     = __floats2half2_rn(binv(v.x, lo, hi), binv(v.y, lo, hi));
        o2[2 * i + 1] = __floats2half2_rn(binv(v.z, lo, hi), binv(v.w, lo, hi));
    }
}

__global__ void xconv_kernel(const float* __restrict__ x, int n4) {
    const float4* x4 = (const float4*)x;
    __half2* o2 = (__half2*)g_Xh;
    for (int i = blockIdx.x * blockDim.x + threadIdx.x; i < n4; i += gridDim.x * blockDim.x) {
        float4 v = x4[i];
        o2[2 * i]     = __floats2half2_rn(v.x, v.y);
        o2[2 * i + 1] = __floats2half2_rn(v.z, v.w);
    }
}

// ---------------------------------------------------------------- GEMM -----
// CTA tile 128(M) x 128(N), BK=64, 3-stage cp.async pipeline, 256 threads,
// 2 CTAs/SM. Warps 2(M) x 4(N); warp tile 64x32 = 4 x 4 mma per k16-step.
// Smem rows 144B: 16B-aligned cp.async dsts, ldmatrix phase-conflict-free.

#define BM 128
#define BN 128
#define BK 64
#define ROWB 144
#define STAGE_A (BM * ROWB)           // 18432
#define STAGE_B (BN * ROWB)           // 18432
#define STAGE   (STAGE_A + STAGE_B)   // 36864
#define NSTG 3
#define GEMM_SMEM (NSTG * STAGE)      // 110592 (x2 CTAs = 216KB/SM)

__device__ __forceinline__ uint32_t smem_u32(const void* p) {
    uint32_t a;
    asm("{ .reg .u64 t; cvta.to.shared.u64 t, %1; cvt.u32.u64 %0, t; }" : "=r"(a) : "l"(p));
    return a;
}
__device__ __forceinline__ void cp16(uint32_t s, const void* g) {
    asm volatile("cp.async.cg.shared.global [%0], [%1], 16;" :: "r"(s), "l"(g));
}
#define CP_COMMIT() asm volatile("cp.async.commit_group;" ::: "memory")
#define CP_WAIT1()  asm volatile("cp.async.wait_group %0;" :: "n"(1) : "memory")

#define LDSM4(r0, r1, r2, r3, addr) \
    asm volatile("ldmatrix.sync.aligned.m8n8.x4.shared.b16 {%0,%1,%2,%3}, [%4];" \
        : "=r"(r0), "=r"(r1), "=r"(r2), "=r"(r3) : "r"(addr))

__device__ __forceinline__ void mma16816(float* d, const uint32_t* a, const uint32_t* b) {
    asm volatile(
        "mma.sync.aligned.m16n8k16.row.col.f32.f16.f16.f32 "
        "{%0,%1,%2,%3}, {%4,%5,%6,%7}, {%8,%9}, {%0,%1,%2,%3};"
        : "+f"(d[0]), "+f"(d[1]), "+f"(d[2]), "+f"(d[3])
        : "r"(a[0]), "r"(a[1]), "r"(a[2]), "r"(a[3]), "r"(b[0]), "r"(b[1]));
}

// One BK=64 stage: A 128x64 fp16 (1024 x 16B chunks), B 128x64 (1024 chunks).
__device__ __forceinline__ void issue_stage(
    uint32_t sb, int stage, const __half* __restrict__ gA,
    const __half* __restrict__ gB, int kt, int tid, int K)
{
    uint32_t sA = sb + stage * STAGE;
    uint32_t sB = sA + STAGE_A;
    const __half* ga = gA + (size_t)kt * BK;
    #pragma unroll
    for (int j = 0; j < 4; j++) {                  // A: 1024 chunks / 256 thr
        int cid = tid + j * 256;
        int r = cid >> 3, c = cid & 7;
        cp16(sA + r * ROWB + c * 16, ga + (size_t)r * K + c * 8);
    }
    const __half* gb = gB + (size_t)kt * BK;
    #pragma unroll
    for (int j = 0; j < 4; j++) {                  // B: 1024 chunks / 256 thr
        int cid = tid + j * 256;
        int r = cid >> 3, c = cid & 7;
        cp16(sB + r * ROWB + c * 16, gb + (size_t)r * K + c * 8);
    }
}

__global__ void __launch_bounds__(256, 2)
gemm_kernel(float* __restrict__ out, const float* __restrict__ bias,
            const __half* __restrict__ A, const __half* __restrict__ B,
            int M, int N, int K)
{
    extern __shared__ char smem[];
    uint32_t sb = smem_u32(smem);

    int tid = threadIdx.x;
    int wid = tid >> 5, L = tid & 31;
    int warpM = wid >> 2, warpN = wid & 3;         // 2(M) x 4(N)

    int NT = N / BN;                               // 32
    int ntile = blockIdx.x % NT;                   // fast N => W stays L2-hot
    int mtile = blockIdx.x / NT;

    const __half* gA = A + (size_t)(mtile * BM) * K;
    const __half* gB = B + (size_t)(ntile * BN) * K;
    int KT = K / BK;                               // 64

    float acc[4][4][4];
    #pragma unroll
    for (int i = 0; i < 4; i++)
        #pragma unroll
        for (int j = 0; j < 4; j++)
            #pragma unroll
            for (int q = 0; q < 4; q++) acc[i][j][q] = 0.f;

    // prologue: fill 2 of 3 stages
    issue_stage(sb, 0, gA, gB, 0, tid, K); CP_COMMIT();
    issue_stage(sb, 1, gA, gB, 1, tid, K); CP_COMMIT();

    // ldmatrix lane offsets (mapping validated R3-R8)
    int aRow = warpM * 64 + (L & 15);              // + mt*16
    int aCol = (L >> 4) << 3;                      // + ks*16
    int jb = L >> 3;
    int bRowBase = warpN * 32 + ((jb >> 1) << 3) + (L & 7);   // + p*16
    int bCol = (jb & 1) << 3;                      // + ks*16

    int st = 0;                                    // stage of current kt
    for (int kt = 0; kt < KT; kt++) {
        CP_WAIT1();
        __syncthreads();

        // issue next-next stage first so cp.async overlaps all 4 ks-steps
        if (kt + 2 < KT) {
            int st2 = st + 2; if (st2 >= NSTG) st2 -= NSTG;
            issue_stage(sb, st2, gA, gB, kt + 2, tid, K);
        }
        CP_COMMIT();                               // commit every iter (tail!)

        uint32_t sA = sb + st * STAGE;
        uint32_t sB = sA + STAGE_A;

        #pragma unroll
        for (int ks = 0; ks < 4; ks++) {           // 4 x k16 within BK=64
            uint32_t aF[4][4], bF[4][2];
            int kc = ks * 16;
            #pragma unroll
            for (int mt = 0; mt < 4; mt++) {
                uint32_t ad = sA + (aRow + mt * 16) * ROWB + (aCol + kc) * 2;
                LDSM4(aF[mt][0], aF[mt][1], aF[mt][2], aF[mt][3], ad);
            }
            #pragma unroll
            for (int p = 0; p < 2; p++) {          // n-tile pairs (2p, 2p+1)
                uint32_t bd = sB + (bRowBase + p * 16) * ROWB + (bCol + kc) * 2;
                uint32_t r0, r1, r2, r3;
                LDSM4(r0, r1, r2, r3, bd);
                bF[2 * p][0] = r0; bF[2 * p][1] = r1;
                bF[2 * p + 1][0] = r2; bF[2 * p + 1][1] = r3;
            }
            #pragma unroll
            for (int mt = 0; mt < 4; mt++)
                #pragma unroll
                for (int nt = 0; nt < 4; nt++)
                    mma16816(acc[mt][nt], aF[mt], bF[nt]);
        }

        if (++st == NSTG) st = 0;
    }

    // ---------------- epilogue: fp32 stores (streaming) + bias ------------
    int rbase = mtile * BM + warpM * 64 + (L >> 2);
    int cbase = ntile * BN + warpN * 32 + (L & 3) * 2;

    float2 bv[4];
    #pragma unroll
    for (int nt = 0; nt < 4; nt++)
        bv[nt] = *(const float2*)(bias + cbase + nt * 8);

    #pragma unroll
    for (int mt = 0; mt < 4; mt++) {
        int r0 = rbase + mt * 16;
        #pragma unroll
        for (int nt = 0; nt < 4; nt++) {
            int c = cbase + nt * 8;
            float2 v0 = { acc[mt][nt][0] + bv[nt].x, acc[mt][nt][1] + bv[nt].y };
            float2 v1 = { acc[mt][nt][2] + bv[nt].x, acc[mt][nt][3] + bv[nt].y };
            __stcs((float2*)(out + (size_t)r0 * N + c), v0);
            __stcs((float2*)(out + (size_t)(r0 + 8) * N + c), v1);
        }
    }
}

// ---------------------------------------------------------------- host -----
extern "C" void kernel_launch(void* const* d_in, const int* in_sizes, int n_in,
                              void* d_out, int out_size)
{
    const float* x    = (const float*)d_in[0];
    const float* w    = (const float*)d_in[1];
    const float* bias = (const float*)d_in[2];
    float* out = (float*)d_out;

    int N  = in_sizes[2];
    int K  = in_sizes[1] / N;
    int M  = in_sizes[0] / K;
    int nw = in_sizes[1];
    int nx = in_sizes[0];

    // Order: gemm stays 4th kernel -> lands in the ncu capture slot.
    xconv_kernel<<<4096, 256>>>(x, nx / 4);
    stats1_kernel<<<1024, 256>>>(w, nw);
    binarize_kernel<<<2048, 256>>>(w, nw / 4, nw);

    void *pXh = nullptr, *pWb = nullptr;
    cudaGetSymbolAddress(&pXh, g_Xh);
    cudaGetSymbolAddress(&pWb, g_Wb);

    cudaFuncSetAttribute(gemm_kernel, cudaFuncAttributeMaxDynamicSharedMemorySize, GEMM_SMEM);

    int grid = (M / BM) * (N / BN);
    gemm_kernel<<<grid, 256, GEMM_SMEM>>>(out, bias, (const __half*)pXh,
                                          (const __half*)pWb, M, N, K);
}

// round 11
// speedup vs baseline: 1.1344x; 1.0357x over previous
#include <cuda_runtime.h>
#include <cuda_fp16.h>
#include <cstdint>

// ============================================================================
// out[M,N] = x[M,K] @ w_bin[N,K]^T + bias[N]
//   w_bin = (w < mean-std || w > mean+std) ? w : sign(w)   (std: ddof=1)
// Shapes: M=16384, K=4096, N=4096 fp32.
// Engine: fp16 convert + mma.sync.m16n8k16 pipelined GEMM (base sm_103 ISA).
// R11: CUTLASS-shape GEMM — 128x128x32 CTA tile, 128 thr (4 warps of 64x64),
//      5-stage cp.async, 2 CTAs/SM, full fragment double-buffering (~230 regs),
//      barrier every 2nd kt. R9 showed smem/tensor co-critical at warp 64x32
//      (0.094 B/MAC); warp 64x64 cuts LDSM traffic 1.5x.
// ============================================================================

#define MAXM 16384
#define MAXN 4096
#define MAXK 4096

__device__ __half g_Xh[(size_t)MAXM * MAXK];   // 128 MiB scratch
__device__ __half g_Wb[(size_t)MAXN * MAXK];   // 32 MiB scratch
__device__ double g_part[2048];

// ---------------------------------------------------------------- stats ----
__global__ void stats1_kernel(const float* __restrict__ w, int n) {
    __shared__ double ss[256], sq[256];
    double s = 0.0, q = 0.0;
    for (int i = blockIdx.x * blockDim.x + threadIdx.x; i < n; i += gridDim.x * blockDim.x) {
        double v = (double)w[i];
        s += v; q += v * v;
    }
    ss[threadIdx.x] = s; sq[threadIdx.x] = q;
    __syncthreads();
    for (int o = 128; o > 0; o >>= 1) {
        if (threadIdx.x < o) { ss[threadIdx.x] += ss[threadIdx.x + o]; sq[threadIdx.x] += sq[threadIdx.x + o]; }
        __syncthreads();
    }
    if (threadIdx.x == 0) { g_part[blockIdx.x * 2] = ss[0]; g_part[blockIdx.x * 2 + 1] = sq[0]; }
}

__device__ __forceinline__ float binv(float w, float lo, float hi) {
    if (w < lo || w > hi) return w;
    return (w > 0.f) ? 1.f : ((w < 0.f) ? -1.f : 0.f);
}

// binarize + final threshold reduce fused (each block redundantly reduces the
// 1024 partials — deterministic, a few us total).
__global__ void binarize_kernel(const float* __restrict__ w, int n4, int n) {
    __shared__ double ss[256], sq[256];
    __shared__ float thr[2];
    double s = 0.0, q = 0.0;
    for (int i = threadIdx.x; i < 1024; i += 256) { s += g_part[2 * i]; q += g_part[2 * i + 1]; }
    ss[threadIdx.x] = s; sq[threadIdx.x] = q;
    __syncthreads();
    for (int o = 128; o > 0; o >>= 1) {
        if (threadIdx.x < o) { ss[threadIdx.x] += ss[threadIdx.x + o]; sq[threadIdx.x] += sq[threadIdx.x + o]; }
        __syncthreads();
    }
    if (threadIdx.x == 0) {
        double mean = ss[0] / (double)n;
        double var  = (sq[0] - ss[0] * ss[0] / (double)n) / (double)(n - 1);
        double sd = sqrt(var);
        thr[0] = (float)(mean - sd);
        thr[1] = (float)(mean + sd);
    }
    __syncthreads();
    float lo = thr[0], hi = thr[1];
    const float4* w4 = (const float4*)w;
    __half2* o2 = (__half2*)g_Wb;
    for (int i = blockIdx.x * blockDim.x + threadIdx.x; i < n4; i += gridDim.x * blockDim.x) {
        float4 v = w4[i];
        o2[2 * i]     = __floats2half2_rn(binv(v.x, lo, hi), binv(v.y, lo, hi));
        o2[2 * i + 1] = __floats2half2_rn(binv(v.z, lo, hi), binv(v.w, lo, hi));
    }
}

__global__ void xconv_kernel(const float* __restrict__ x, int n4) {
    const float4* x4 = (const float4*)x;
    __half2* o2 = (__half2*)g_Xh;
    for (int i = blockIdx.x * blockDim.x + threadIdx.x; i < n4; i += gridDim.x * blockDim.x) {
        float4 v = x4[i];
        o2[2 * i]     = __floats2half2_rn(v.x, v.y);
        o2[2 * i + 1] = __floats2half2_rn(v.z, v.w);
    }
}

// ---------------------------------------------------------------- GEMM -----
// CTA tile 128x128, BK=32, 5-stage cp.async, 128 threads (4 warps 2x2),
// warp tile 64x64, fragment double-buffering, 2 CTAs/SM.
// Smem rows 80B (32 fp16 + 16 pad): 16B-aligned, ldmatrix conflict-free
// (80*8 rows mod 128 covers all banks — validated R3/R4).

#define BM 128
#define BN 128
#define BK 32
#define ROWB 80
#define STAGE_A (BM * ROWB)           // 10240
#define STAGE_B (BN * ROWB)           // 10240
#define STAGE   (STAGE_A + STAGE_B)   // 20480
#define NSTG 5
#define GEMM_SMEM (NSTG * STAGE)      // 102400 (x2 CTAs = 200KB/SM)

__device__ __forceinline__ uint32_t smem_u32(const void* p) {
    uint32_t a;
    asm("{ .reg .u64 t; cvta.to.shared.u64 t, %1; cvt.u32.u64 %0, t; }" : "=r"(a) : "l"(p));
    return a;
}
__device__ __forceinline__ void cp16(uint32_t s, const void* g) {
    asm volatile("cp.async.cg.shared.global [%0], [%1], 16;" :: "r"(s), "l"(g));
}
#define CP_COMMIT() asm volatile("cp.async.commit_group;" ::: "memory")
#define CP_WAITG(n) asm volatile("cp.async.wait_group %0;" :: "n"(n) : "memory")

#define LDSM4(r0, r1, r2, r3, addr) \
    asm volatile("ldmatrix.sync.aligned.m8n8.x4.shared.b16 {%0,%1,%2,%3}, [%4];" \
        : "=r"(r0), "=r"(r1), "=r"(r2), "=r"(r3) : "r"(addr))

__device__ __forceinline__ void mma16816(float* d, const uint32_t* a, const uint32_t* b) {
    asm volatile(
        "mma.sync.aligned.m16n8k16.row.col.f32.f16.f16.f32 "
        "{%0,%1,%2,%3}, {%4,%5,%6,%7}, {%8,%9}, {%0,%1,%2,%3};"
        : "+f"(d[0]), "+f"(d[1]), "+f"(d[2]), "+f"(d[3])
        : "r"(a[0]), "r"(a[1]), "r"(a[2]), "r"(a[3]), "r"(b[0]), "r"(b[1]));
}

// One BK=32 stage: A 128x32 fp16 (512 x 16B chunks), B 128x32 (512 chunks).
__device__ __forceinline__ void issue_stage(
    uint32_t sb, int stage, const __half* __restrict__ gA,
    const __half* __restrict__ gB, int kt, int tid, int K)
{
    uint32_t sA = sb + stage * STAGE;
    uint32_t sB = sA + STAGE_A;
    const __half* ga = gA + (size_t)kt * BK;
    #pragma unroll
    for (int j = 0; j < 4; j++) {                  // A: 512 chunks / 128 thr
        int cid = tid + j * 128;
        int r = cid >> 2, c = cid & 3;
        cp16(sA + r * ROWB + c * 16, ga + (size_t)r * K + c * 8);
    }
    const __half* gb = gB + (size_t)kt * BK;
    #pragma unroll
    for (int j = 0; j < 4; j++) {                  // B: 512 chunks / 128 thr
        int cid = tid + j * 128;
        int r = cid >> 2, c = cid & 3;
        cp16(sB + r * ROWB + c * 16, gb + (size_t)r * K + c * 8);
    }
}

__global__ void __launch_bounds__(128, 2)
gemm_kernel(float* __restrict__ out, const float* __restrict__ bias,
            const __half* __restrict__ A, const __half* __restrict__ B,
            int M, int N, int K)
{
    extern __shared__ char smem[];
    uint32_t sb = smem_u32(smem);

    int tid = threadIdx.x;
    int wid = tid >> 5, L = tid & 31;
    int warpM = wid >> 1, warpN = wid & 1;         // 2(M) x 2(N)

    int NT = N / BN;                               // 32
    int ntile = blockIdx.x % NT;                   // fast N => W stays L2-hot
    int mtile = blockIdx.x / NT;

    const __half* gA = A + (size_t)(mtile * BM) * K;
    const __half* gB = B + (size_t)(ntile * BN) * K;
    int KT = K / BK;                               // 128

    float acc[4][8][4];
    #pragma unroll
    for (int i = 0; i < 4; i++)
        #pragma unroll
        for (int j = 0; j < 8; j++)
            #pragma unroll
            for (int q = 0; q < 4; q++) acc[i][j][q] = 0.f;

    // prologue: fill 3 of 5 stages (issue depth 3)
    issue_stage(sb, 0, gA, gB, 0, tid, K); CP_COMMIT();
    issue_stage(sb, 1, gA, gB, 1, tid, K); CP_COMMIT();
    issue_stage(sb, 2, gA, gB, 2, tid, K); CP_COMMIT();

    // ldmatrix lane offsets (warp 64x64 mapping validated R6)
    int aRow = warpM * 64 + (L & 15);              // + mt*16
    int aCol = (L >> 4) << 3;                      // + ks*16
    int jb = L >> 3;
    int bRowBase = warpN * 64 + ((jb >> 1) << 3) + (L & 7);   // + p*16
    int bCol = (jb & 1) << 3;                      // + ks*16

    uint32_t aF[2][4][4], bF[2][8][2];

    int st = 0;                                    // stage of current kt
    for (int kt = 0; kt < KT; kt++) {
        if (!(kt & 1)) {
            // completes stages kt and kt+1 for every thread, then one barrier
            // makes both visible CTA-wide; odd kt needs no wait/barrier.
            CP_WAITG(1);
            __syncthreads();
        }

        uint32_t sA = sb + st * STAGE;
        uint32_t sB = sA + STAGE_A;

        // prefetch ks=0 fragments
        #pragma unroll
        for (int mt = 0; mt < 4; mt++) {
            uint32_t ad = sA + (aRow + mt * 16) * ROWB + aCol * 2;
            LDSM4(aF[0][mt][0], aF[0][mt][1], aF[0][mt][2], aF[0][mt][3], ad);
        }
        #pragma unroll
        for (int p = 0; p < 4; p++) {
            uint32_t bd = sB + (bRowBase + p * 16) * ROWB + bCol * 2;
            uint32_t r0, r1, r2, r3;
            LDSM4(r0, r1, r2, r3, bd);
            bF[0][2 * p][0] = r0; bF[0][2 * p][1] = r1;
            bF[0][2 * p + 1][0] = r2; bF[0][2 * p + 1][1] = r3;
        }

        // issue stage kt+3 (write target >= 2 stages from any laggard's reads)
        if (kt + 3 < KT) {
            int st3 = st + 3; if (st3 >= NSTG) st3 -= NSTG;
            issue_stage(sb, st3, gA, gB, kt + 3, tid, K);
        }
        CP_COMMIT();                               // commit every iter (tail!)

        #pragma unroll
        for (int ks = 0; ks < 2; ks++) {           // 2 x k16 within BK=32
            int cur = ks & 1, nxt = cur ^ 1;
            if (ks < 1) {                          // prefetch ks=1 fragments
                int kc = 16;
                #pragma unroll
                for (int mt = 0; mt < 4; mt++) {
                    uint32_t ad = sA + (aRow + mt * 16) * ROWB + (aCol + kc) * 2;
                    LDSM4(aF[nxt][mt][0], aF[nxt][mt][1], aF[nxt][mt][2], aF[nxt][mt][3], ad);
                }
                #pragma unroll
                for (int p = 0; p < 4; p++) {
                    uint32_t bd = sB + (bRowBase + p * 16) * ROWB + (bCol + kc) * 2;
                    uint32_t r0, r1, r2, r3;
                    LDSM4(r0, r1, r2, r3, bd);
                    bF[nxt][2 * p][0] = r0; bF[nxt][2 * p][1] = r1;
                    bF[nxt][2 * p + 1][0] = r2; bF[nxt][2 * p + 1][1] = r3;
                }
            }
            #pragma unroll
            for (int mt = 0; mt < 4; mt++)
                #pragma unroll
                for (int nt = 0; nt < 8; nt++)
                    mma16816(acc[mt][nt], aF[cur][mt], bF[cur][nt]);
        }

        if (++st == NSTG) st = 0;
    }

    // ---------------- epilogue: fp32 stores (streaming) + bias ------------
    int rbase = mtile * BM + warpM * 64 + (L >> 2);
    int cbase = ntile * BN + warpN * 64 + (L & 3) * 2;

    float2 bv[8];
    #pragma unroll
    for (int nt = 0; nt < 8; nt++)
        bv[nt] = *(const float2*)(bias + cbase + nt * 8);

    #pragma unroll
    for (int mt = 0; mt < 4; mt++) {
        int r0 = rbase + mt * 16;
        #pragma unroll
        for (int nt = 0; nt < 8; nt++) {
            int c = cbase + nt * 8;
            float2 v0 = { acc[mt][nt][0] + bv[nt].x, acc[mt][nt][1] + bv[nt].y };
            float2 v1 = { acc[mt][nt][2] + bv[nt].x, acc[mt][nt][3] + bv[nt].y };
            __stcs((float2*)(out + (size_t)r0 * N + c), v0);
            __stcs((float2*)(out + (size_t)(r0 + 8) * N + c), v1);
        }
    }
}

// ---------------------------------------------------------------- host -----
extern "C" void kernel_launch(void* const* d_in, const int* in_sizes, int n_in,
                              void* d_out, int out_size)
{
    const float* x    = (const float*)d_in[0];
    const float* w    = (const float*)d_in[1];
    const float* bias = (const float*)d_in[2];
    float* out = (float*)d_out;

    int N  = in_sizes[2];
    int K  = in_sizes[1] / N;
    int M  = in_sizes[0] / K;
    int nw = in_sizes[1];
    int nx = in_sizes[0];

    // Order: gemm stays 4th kernel -> lands in the ncu capture slot.
    xconv_kernel<<<4096, 256>>>(x, nx / 4);
    stats1_kernel<<<1024, 256>>>(w, nw);
    binarize_kernel<<<2048, 256>>>(w, nw / 4, nw);

    void *pXh = nullptr, *pWb = nullptr;
    cudaGetSymbolAddress(&pXh, g_Xh);
    cudaGetSymbolAddress(&pWb, g_Wb);

    cudaFuncSetAttribute(gemm_kernel, cudaFuncAttributeMaxDynamicSharedMemorySize, GEMM_SMEM);

    int grid = (M / BM) * (N / BN);
    gemm_kernel<<<grid, 128, GEMM_SMEM>>>(out, bias, (const __half*)pXh,
                                          (const __half*)pWb, M, N, K);
}